// round 15
// baseline (speedup 1.0000x reference)
#include <cuda_runtime.h>
#include <cuda_bf16.h>
#include <math.h>
#include <cstdint>

// ---------------- problem constants ----------------
#define BATCH 512
#define SEQL  20
#define NNODE 16
#define EPS_  32
#define HDIM  128
#define VOCAB 100000
#define NTOT  (BATCH*NNODE)        // 8192
#define NEDGE (BATCH*EPS_)         // 16384
#define NOUT  (VOCAB-1)            // 99999
#define NT_   782                  // ceil(NOUT/128)
#define NPAD  (NT_*128)            // 100096 padded B rows
#define NJOBS (4*NT_)              // 3128
#define PGRID 148

// ---------------- device scratch (no allocs allowed) ----------------
__device__ float g_x[NTOT*HDIM];
__device__ float g_m[NTOT*HDIM];
__device__ float g_agg[NTOT*HDIM];
__device__ float g_gi[NTOT*3*HDIM];
__device__ float g_gh[NTOT*3*HDIM];
__device__ float g_gT[HDIM*HDIM];
__device__ float g_w1T[HDIM*HDIM];
__device__ float g_w2T[HDIM*HDIM];
__device__ float g_wtT[2*HDIM*HDIM];
__device__ __nv_bfloat16 g_bhi[(size_t)NPAD*HDIM];   // emb[1:] hi split (padded)
__device__ __nv_bfloat16 g_blo[(size_t)NPAD*HDIM];   // emb[1:] lo split
__device__ __nv_bfloat16 g_ahi[BATCH*HDIM];          // afin hi split
__device__ __nv_bfloat16 g_alo[BATCH*HDIM];          // afin lo split

// ---------------- helpers ----------------
__device__ __forceinline__ uint32_t smem_to_u32(const void* p) {
    uint32_t a;
    asm("{ .reg .u64 t; cvta.to.shared.u64 t, %1; cvt.u32.u64 %0, t; }" : "=r"(a) : "l"(p));
    return a;
}

// hi = bf16 bits via truncation; lo = RN(x - hi)  (exact 16+8-bit split)
__device__ __forceinline__ void split2(float x, float y, uint32_t& hi, uint32_t& lo) {
    uint32_t ux = __float_as_uint(x), uy = __float_as_uint(y);
    hi = __byte_perm(ux, uy, 0x7632);
    float lx = x - __uint_as_float(ux & 0xffff0000u);
    float ly = y - __uint_as_float(uy & 0xffff0000u);
    __nv_bfloat162 t = __floats2bfloat162_rn(lx, ly);
    lo = *reinterpret_cast<uint32_t*>(&t);
}

#define MMA_BF16(d, a, b)                                                        \
    asm volatile("mma.sync.aligned.m16n8k16.row.col.f32.bf16.bf16.f32 "         \
                 "{%0,%1,%2,%3}, {%4,%5,%6,%7}, {%8,%9}, {%0,%1,%2,%3};"        \
                 : "+f"((d)[0]), "+f"((d)[1]), "+f"((d)[2]), "+f"((d)[3])        \
                 : "r"((a)[0]), "r"((a)[1]), "r"((a)[2]), "r"((a)[3]),           \
                   "r"((b)[0]), "r"((b)[1]))

#define CP_ASYNC16(daddr, gptr) \
    asm volatile("cp.async.cg.shared.global [%0], [%1], 16;" :: "r"(daddr), "l"(gptr))
#define CP_COMMIT() asm volatile("cp.async.commit_group;" ::: "memory")
#define CP_WAIT0()  asm volatile("cp.async.wait_group 0;"  ::: "memory")

// padded bf16 tile: 128 rows x 128 cols, pitch 272B -> conflict-free frag loads
#define ROWB     272
#define TILE_B   34816          // 128*272
#define NTHR     512            // 16 warps: 4 (M) x 4 (N); warp tile 32x32

// ---- MMA inner loop: 128x128x128 split-bf16, 3 passes, 16 warps ----
__device__ __forceinline__ void mma_compute(
    const char* aHb, const char* aLb, const char* bHb, const char* bLb,
    int wm, int wn, int g, int tig, float acc[2][4][4])
{
    const char* aH = aHb + (uint32_t)(wm * 32 + g) * ROWB + tig * 4;
    const char* aL = aLb + (uint32_t)(wm * 32 + g) * ROWB + tig * 4;
    const char* bH = bHb + (uint32_t)(wn * 32 + g) * ROWB + tig * 4;
    const char* bL = bLb + (uint32_t)(wn * 32 + g) * ROWB + tig * 4;

    #pragma unroll
    for (int ks = 0; ks < 8; ++ks) {
        const int kb = ks * 32;
        uint32_t ah[2][4], al[2][4], bh[4][2], bl[4][2];
        #pragma unroll
        for (int mf = 0; mf < 2; ++mf) {
            const char* p = aH + mf * (16 * ROWB) + kb;
            ah[mf][0] = *reinterpret_cast<const uint32_t*>(p);
            ah[mf][1] = *reinterpret_cast<const uint32_t*>(p + 8 * ROWB);
            ah[mf][2] = *reinterpret_cast<const uint32_t*>(p + 16);
            ah[mf][3] = *reinterpret_cast<const uint32_t*>(p + 8 * ROWB + 16);
            const char* q = aL + mf * (16 * ROWB) + kb;
            al[mf][0] = *reinterpret_cast<const uint32_t*>(q);
            al[mf][1] = *reinterpret_cast<const uint32_t*>(q + 8 * ROWB);
            al[mf][2] = *reinterpret_cast<const uint32_t*>(q + 16);
            al[mf][3] = *reinterpret_cast<const uint32_t*>(q + 8 * ROWB + 16);
        }
        #pragma unroll
        for (int nf = 0; nf < 4; ++nf) {
            const char* p = bH + nf * (8 * ROWB) + kb;
            bh[nf][0] = *reinterpret_cast<const uint32_t*>(p);
            bh[nf][1] = *reinterpret_cast<const uint32_t*>(p + 16);
            const char* q = bL + nf * (8 * ROWB) + kb;
            bl[nf][0] = *reinterpret_cast<const uint32_t*>(q);
            bl[nf][1] = *reinterpret_cast<const uint32_t*>(q + 16);
        }
        #pragma unroll
        for (int mf = 0; mf < 2; ++mf)
            #pragma unroll
            for (int nf = 0; nf < 4; ++nf) {
                MMA_BF16(acc[mf][nf], ah[mf], bh[nf]);   // hi*hi
                MMA_BF16(acc[mf][nf], ah[mf], bl[nf]);   // hi*lo
                MMA_BF16(acc[mf][nf], al[mf], bh[nf]);   // lo*hi
            }
    }
}

// ---------------- generic small GEMM: fp32 in, split in-kernel ----------------
#define SM_AHI   0
#define SM_ALO   34816
#define SM_BHI   69632
#define SM_BLO   104448
#define SM_TOTAL 139264

__device__ __forceinline__ void gemm_tile_body(
    const float* __restrict__ A, const float* __restrict__ B,
    float* __restrict__ C, int N, int mBase, int nBase, char* sm)
{
    const int tid  = threadIdx.x, wid = tid >> 5, lane = tid & 31;
    const int g    = lane >> 2, tig = lane & 3;

    #pragma unroll
    for (int it = 0; it < 8; ++it) {
        int idx = tid + it * NTHR;         // 4096 = 128 rows x 32 float4
        int r = idx >> 5, c4 = (idx & 31) << 2;
        uint32_t soff = (uint32_t)r * ROWB + (uint32_t)c4 * 2;

        float4 v = *reinterpret_cast<const float4*>(A + (size_t)(mBase + r) * 128 + c4);
        uint32_t h0, l0, h1, l1;
        split2(v.x, v.y, h0, l0);
        split2(v.z, v.w, h1, l1);
        *reinterpret_cast<uint2*>(sm + SM_AHI + soff) = make_uint2(h0, h1);
        *reinterpret_cast<uint2*>(sm + SM_ALO + soff) = make_uint2(l0, l1);

        int n = nBase + r;
        float4 w = make_float4(0.f, 0.f, 0.f, 0.f);
        if (n < N) w = *reinterpret_cast<const float4*>(B + (size_t)n * 128 + c4);
        split2(w.x, w.y, h0, l0);
        split2(w.z, w.w, h1, l1);
        *reinterpret_cast<uint2*>(sm + SM_BHI + soff) = make_uint2(h0, h1);
        *reinterpret_cast<uint2*>(sm + SM_BLO + soff) = make_uint2(l0, l1);
    }
    __syncthreads();

    const int wm = wid >> 2, wn = wid & 3;
    float acc[2][4][4];
    #pragma unroll
    for (int mf = 0; mf < 2; ++mf)
        #pragma unroll
        for (int nf = 0; nf < 4; ++nf)
            #pragma unroll
            for (int e = 0; e < 4; ++e) acc[mf][nf][e] = 0.f;

    mma_compute(sm + SM_AHI, sm + SM_ALO, sm + SM_BHI, sm + SM_BLO,
                wm, wn, g, tig, acc);

    // N here is 128 or 384 (even) and C is 16B-aligned -> float2 is safe
    #pragma unroll
    for (int mf = 0; mf < 2; ++mf) {
        int row0 = mBase + wm * 32 + mf * 16 + g;
        #pragma unroll
        for (int nf = 0; nf < 4; ++nf) {
            int col = nBase + wn * 32 + nf * 8 + tig * 2;
            if (col < N) {
                *reinterpret_cast<float2*>(&C[(size_t)row0 * N + col]) =
                    make_float2(acc[mf][nf][0], acc[mf][nf][1]);
                *reinterpret_cast<float2*>(&C[(size_t)(row0 + 8) * N + col]) =
                    make_float2(acc[mf][nf][2], acc[mf][nf][3]);
            }
        }
    }
}

__global__ __launch_bounds__(NTHR) void gemm_tc(
    const float* __restrict__ A, const float* __restrict__ B,
    float* __restrict__ C, int N)
{
    extern __shared__ char sm[];
    gemm_tile_body(A, B, C, N, blockIdx.y << 7, blockIdx.x << 7, sm);
}

// fused gi/gh: grid (6, 64); bx<3 -> gi = agg@Wih^T, else gh = x@Whh^T
__global__ __launch_bounds__(NTHR) void gemm_gates(
    const float* __restrict__ Wih, const float* __restrict__ Whh)
{
    extern __shared__ char sm[];
    int sel = blockIdx.x / 3, nb = blockIdx.x % 3;
    const float* A = sel ? g_x : g_agg;
    const float* B = sel ? Whh : Wih;
    float*       C = sel ? g_gh : g_gi;
    gemm_tile_body(A, B, C, 3 * HDIM, blockIdx.y << 7, nb << 7, sm);
}

// ---------------- persistent vocab GEMM (pre-split bf16, double-buffered) ----------------
#define SB(p)    (TILE_B * 2 + (p) * (TILE_B * 2))
#define SM_PTOT  (TILE_B * 6)                         // 208896

__device__ __forceinline__ void ld_tile_bf16(
    const __nv_bfloat16* __restrict__ src, int row0, uint32_t dstbase, int tid)
{
    #pragma unroll
    for (int it = 0; it < 4; ++it) {
        int idx = tid + it * NTHR;         // 2048 chunks of 16B
        int r = idx >> 4, c16 = idx & 15;
        uint32_t daddr = dstbase + (uint32_t)r * ROWB + c16 * 16;
        CP_ASYNC16(daddr, src + (size_t)(row0 + r) * 128 + c16 * 8);
    }
}

__global__ __launch_bounds__(NTHR) void gemm_scores(float* __restrict__ C)
{
    extern __shared__ char sm[];
    uint32_t smb = smem_to_u32(sm);
    const int tid = threadIdx.x, wid = tid >> 5, lane = tid & 31;
    const int g = lane >> 2, tig = lane & 3;
    const int wm = wid >> 2, wn = wid & 3;

    int m_cur = 0;                          // blockIdx.x < 148 < NT_
    ld_tile_bf16(g_ahi, 0, smb + 0,      tid);
    ld_tile_bf16(g_alo, 0, smb + TILE_B, tid);
    ld_tile_bf16(g_bhi, blockIdx.x << 7, smb + SB(0),          tid);
    ld_tile_bf16(g_blo, blockIdx.x << 7, smb + SB(0) + TILE_B, tid);
    CP_COMMIT();
    int p = 0;

    for (int j = blockIdx.x; j < NJOBS; j += PGRID) {
        const int n = j - m_cur * NT_;

        // SB(p) (and A on transitions) ready; the barrier also proves every
        // thread finished the PREVIOUS job -> SB(1-p) is safe to refill.
        CP_WAIT0();
        __syncthreads();

        const int jn = j + PGRID;
        const bool havenext = jn < NJOBS;
        const int mn = havenext ? jn / NT_ : -1;

        if (havenext && mn == m_cur) {       // prefetch next B during MMA
            int nn = jn - mn * NT_;
            ld_tile_bf16(g_bhi, nn << 7, smb + SB(1 - p),          tid);
            ld_tile_bf16(g_blo, nn << 7, smb + SB(1 - p) + TILE_B, tid);
            CP_COMMIT();
        }

        float acc[2][4][4];
        #pragma unroll
        for (int mf = 0; mf < 2; ++mf)
            #pragma unroll
            for (int nf = 0; nf < 4; ++nf)
                #pragma unroll
                for (int e = 0; e < 4; ++e) acc[mf][nf][e] = 0.f;

        mma_compute(sm + 0, sm + TILE_B, sm + SB(p), sm + SB(p) + TILE_B,
                    wm, wn, g, tig, acc);

        // direct epilogue: SCALAR stores (NOUT=99999 is odd -> row base parity
        // alternates; float2 would be 4B-aligned half the time = trap).
        // Lane quads still cover each 32B sector fully -> no amplification.
        const int mB = m_cur << 7, nB = n << 7;
        #pragma unroll
        for (int mf = 0; mf < 2; ++mf) {
            int row0 = mB + wm * 32 + mf * 16 + g;
            #pragma unroll
            for (int nf = 0; nf < 4; ++nf) {
                int col = nB + wn * 32 + nf * 8 + tig * 2;
                size_t r0 = (size_t)row0 * NOUT, r1 = (size_t)(row0 + 8) * NOUT;
                if (col < NOUT)     { C[r0 + col]     = acc[mf][nf][0];
                                      C[r1 + col]     = acc[mf][nf][2]; }
                if (col + 1 < NOUT) { C[r0 + col + 1] = acc[mf][nf][1];
                                      C[r1 + col + 1] = acc[mf][nf][3]; }
            }
        }

        if (havenext && mn != m_cur) {       // rare m transition: reload A + next B
            __syncthreads();                 // all mma reads of A done
            m_cur = mn;
            ld_tile_bf16(g_ahi, m_cur << 7, smb + 0,      tid);
            ld_tile_bf16(g_alo, m_cur << 7, smb + TILE_B, tid);
            int nn = jn - mn * NT_;
            ld_tile_bf16(g_bhi, nn << 7, smb + SB(1 - p),          tid);
            ld_tile_bf16(g_blo, nn << 7, smb + SB(1 - p) + TILE_B, tid);
            CP_COMMIT();
        }
        p ^= 1;
    }
}

// ---------------- prep: zero agg, transposes, emb split, x gather ----------------
__global__ void prep_kernel(const int* __restrict__ items,
                            const float* __restrict__ emb,
                            const float* __restrict__ ggnn,
                            const float* __restrict__ W1,
                            const float* __restrict__ W2,
                            const float* __restrict__ Wt) {
    int i = blockIdx.x * 256 + threadIdx.x;
    if (i < NPAD * HDIM) {                     // emb[1:] split, zero-padded rows
        int n = i >> 7, c = i & 127;
        float v = (n < NOUT) ? emb[(size_t)(n + 1) * 128 + c] : 0.f;
        uint32_t u = __float_as_uint(v);
        __nv_bfloat16_raw hr; hr.x = (unsigned short)(u >> 16);
        g_bhi[i] = __nv_bfloat16(hr);
        g_blo[i] = __float2bfloat16(v - __uint_as_float(u & 0xffff0000u));
    }
    if (i < NTOT * HDIM) {
        g_agg[i] = 0.f;
        int node = i >> 7, h = i & 127;
        g_x[i] = emb[(size_t)items[node] * 128 + h];
    }
    if (i < HDIM * HDIM) {
        int r = i >> 7, c = i & 127;
        g_gT[c * 128 + r]  = ggnn[i];
        g_w1T[c * 128 + r] = W1[i];
        g_w2T[c * 128 + r] = W2[i];
    }
    if (i < 2 * HDIM * HDIM) {                 // Wt [128][256]
        int r = i >> 8, c = i & 255;
        g_wtT[c * 128 + r] = Wt[i];
    }
}

__global__ void scatter_kernel(const int* __restrict__ ei) {
    int i = blockIdx.x * 256 + threadIdx.x;    // NEDGE*128 total
    int e = i >> 7, h = i & 127;
    int s = ei[e], d = ei[NEDGE + e];
    atomicAdd(&g_agg[(size_t)d * HDIM + h], g_m[(size_t)s * HDIM + h]);
}

// ---------------- fused GRU + hidden + attention + transform + LN ----------------
__device__ __forceinline__ float blockSum128(float v, float* red) {
    #pragma unroll
    for (int o = 16; o > 0; o >>= 1) v += __shfl_xor_sync(0xffffffffu, v, o);
    if ((threadIdx.x & 31) == 0) red[threadIdx.x >> 5] = v;
    __syncthreads();
    v = red[0] + red[1] + red[2] + red[3];
    __syncthreads();
    return v;
}

__global__ __launch_bounds__(128) void attn_kernel(
    const int* __restrict__ items, const int* __restrict__ seq,
    const int* __restrict__ mask,  const float* __restrict__ emb,
    const float* __restrict__ bih, const float* __restrict__ bhh,
    const float* __restrict__ b1,  const float* __restrict__ b2,
    const float* __restrict__ w3,  const float* __restrict__ bt,
    const float* __restrict__ gamma, const float* __restrict__ beta)
{
    int b = blockIdx.x, h = threadIdx.x;
    __shared__ float xg[NNODE][HDIM];
    __shared__ float hid[SEQL][HDIM];
    __shared__ float a_s[HDIM], ht_s[HDIM];
    __shared__ float red[4];
    __shared__ int it_s[NNODE];
    __shared__ int msk[SEQL];
    __shared__ int sl;

    if (h < NNODE) it_s[h] = items[b * NNODE + h];
    if (h < SEQL)  msk[h]  = mask[b * SEQL + h];
    if (h == 0) {
        int c = 0;
        for (int l = 0; l < SEQL; ++l) c += mask[b * SEQL + l];
        sl = c - 1;
    }
    __syncthreads();

    float bi0 = bih[h], bi1 = bih[128 + h], bi2 = bih[256 + h];
    float bh0 = bhh[h], bh1 = bhh[128 + h], bh2 = bhh[256 + h];
    #pragma unroll 4
    for (int ni = 0; ni < NNODE; ++ni) {
        size_t node = (size_t)b * NNODE + ni;
        const float* gi = g_gi + node * 384;
        const float* gh = g_gh + node * 384;
        float r = 1.f / (1.f + expf(-((gi[h] + bi0) + (gh[h] + bh0))));
        float z = 1.f / (1.f + expf(-((gi[128 + h] + bi1) + (gh[128 + h] + bh1))));
        float nn = tanhf((gi[256 + h] + bi2) + r * (gh[256 + h] + bh2));
        float xo = g_x[node * HDIM + h];
        xg[ni][h] = (1.f - z) * nn + z * xo;
    }
    __syncthreads();

    for (int l = 0; l < SEQL; ++l) {
        int s = seq[b * SEQL + l];
        float v = 0.f;
        if (s != 0) {
            int found = -1;
            #pragma unroll
            for (int ni = 0; ni < NNODE; ++ni)
                if (found < 0 && it_s[ni] == s) found = ni;
            v = (found >= 0) ? xg[found][h] : emb[(size_t)s * HDIM + h];
        }
        hid[l][h] = v;
    }
    __syncthreads();
    ht_s[h] = hid[sl][h];
    __syncthreads();

    float q1v = b1[h];
    #pragma unroll 8
    for (int k = 0; k < HDIM; ++k) q1v += ht_s[k] * g_w1T[k * 128 + h];

    float w3v = w3[h];
    float acc = 0.f;
    for (int l = 0; l < SEQL; ++l) {
        float q2v = b2[h];
        #pragma unroll 8
        for (int k = 0; k < HDIM; ++k) q2v += hid[l][k] * g_w2T[k * 128 + h];
        float s = 1.f / (1.f + expf(-(q1v + q2v)));
        float alpha = blockSum128(s * w3v, red);
        if (msk[l]) acc += alpha * hid[l][h];
    }
    a_s[h] = acc;
    __syncthreads();

    float av = bt[h];
    #pragma unroll 8
    for (int k = 0; k < HDIM; ++k) av += a_s[k]  * g_wtT[k * 128 + h];
    #pragma unroll 8
    for (int k = 0; k < HDIM; ++k) av += ht_s[k] * g_wtT[(128 + k) * 128 + h];

    float mu  = blockSum128(av, red) * (1.f / HDIM);
    float d   = av - mu;
    float var = blockSum128(d * d, red) * (1.f / HDIM);
    float v   = d * rsqrtf(var + 1e-5f) * gamma[h] + beta[h];

    uint32_t u = __float_as_uint(v);
    __nv_bfloat16_raw hr; hr.x = (unsigned short)(u >> 16);
    g_ahi[b * HDIM + h] = __nv_bfloat16(hr);
    g_alo[b * HDIM + h] = __float2bfloat16(v - __uint_as_float(u & 0xffff0000u));
}

// ---------------- launch ----------------
extern "C" void kernel_launch(void* const* d_in, const int* in_sizes, int n_in,
                              void* d_out, int out_size) {
    const int*   items = (const int*)  d_in[0];
    const int*   eidx  = (const int*)  d_in[1];
    const int*   seq   = (const int*)  d_in[2];
    const int*   mask  = (const int*)  d_in[3];
    const float* emb   = (const float*)d_in[4];
    const float* ggnn  = (const float*)d_in[5];
    const float* Wih   = (const float*)d_in[6];
    const float* Whh   = (const float*)d_in[7];
    const float* bih   = (const float*)d_in[8];
    const float* bhh   = (const float*)d_in[9];
    const float* W1    = (const float*)d_in[10];
    const float* b1    = (const float*)d_in[11];
    const float* W2    = (const float*)d_in[12];
    const float* b2    = (const float*)d_in[13];
    const float* w3    = (const float*)d_in[14];
    const float* Wt    = (const float*)d_in[15];
    const float* bt    = (const float*)d_in[16];
    const float* gamma = (const float*)d_in[17];
    const float* beta  = (const float*)d_in[18];
    float* out = (float*)d_out;

    float *px, *pgT, *pm;
    cudaGetSymbolAddress((void**)&px,  g_x);
    cudaGetSymbolAddress((void**)&pgT, g_gT);
    cudaGetSymbolAddress((void**)&pm,  g_m);

    cudaFuncSetAttribute(gemm_tc,     cudaFuncAttributeMaxDynamicSharedMemorySize, SM_TOTAL);
    cudaFuncSetAttribute(gemm_gates,  cudaFuncAttributeMaxDynamicSharedMemorySize, SM_TOTAL);
    cudaFuncSetAttribute(gemm_scores, cudaFuncAttributeMaxDynamicSharedMemorySize, SM_PTOT);

    const int prep_grid = (NPAD * HDIM + 255) / 256;

    prep_kernel<<<prep_grid, 256>>>(items, emb, ggnn, W1, W2, Wt);        // 0
    gemm_tc<<<dim3(1, 64), NTHR, SM_TOTAL>>>(px, pgT, pm, HDIM);          // 1
    scatter_kernel<<<NEDGE/2, 256>>>(eidx);                               // 2
    gemm_gates<<<dim3(6, 64), NTHR, SM_TOTAL>>>(Wih, Whh);                // 3
    attn_kernel<<<BATCH, 128>>>(items, seq, mask, emb, bih, bhh,          // 4
                                b1, b2, w3, bt, gamma, beta);
    gemm_scores<<<PGRID, NTHR, SM_PTOT>>>(out);                           // 5
}